// round 11
// baseline (speedup 1.0000x reference)
#include <cuda_runtime.h>
#include <cuda_bf16.h>
#include <math.h>
#include <stdint.h>

// ---------------- problem constants ----------------
#define BSZ   64
#define FDIM  256
#define MDIM  128
#define KC    32                    // K elements per chunk
#define NCHUNK (FDIM / KC)          // 8
#define PITCHB 80                   // bytes per smem row (64B data + 16B pad, LDSM conflict-free)
#define TILEB  (MDIM * PITCHB)      // 10240 B per operand tile
#define BUFB   (4 * TILEB)          // 40960 B per stage (Ahi,Alo,Bhi,Blo)
#define SMEM_DYN (2 * BUFB)         // 81920 B double-buffered

#define NPAIR (BSZ * (BSZ + 1) / 2) // 2080
#define STARTROW(x) ((x) * BSZ - (x) * ((x) - 1) / 2)

// bf16 hi/lo scratch, K-major: [z][batch][m][f]  (8 MB each)
__device__ __nv_bfloat16 g_hi[2u * BSZ * MDIM * FDIM];
__device__ __nv_bfloat16 g_lo[2u * BSZ * MDIM * FDIM];

// ---------------- helpers ----------------
__device__ __forceinline__ uint32_t smem_u32(const void* p) {
    uint32_t a;
    asm("{ .reg .u64 t; cvta.to.shared.u64 t, %1; cvt.u32.u64 %0, t; }" : "=r"(a) : "l"(p));
    return a;
}
__device__ __forceinline__ void cp16(uint32_t s, const void* g) {
    asm volatile("cp.async.cg.shared.global [%0], [%1], 16;" :: "r"(s), "l"(g));
}
#define CP_COMMIT() asm volatile("cp.async.commit_group;" ::: "memory")
#define CP_WAIT1()  asm volatile("cp.async.wait_group 1;" ::: "memory")
#define CP_WAIT0()  asm volatile("cp.async.wait_group 0;" ::: "memory")

__device__ __forceinline__ void ldsm_x4(uint32_t* r, uint32_t addr) {
    asm volatile("ldmatrix.sync.aligned.m8n8.x4.shared.b16 {%0,%1,%2,%3}, [%4];"
                 : "=r"(r[0]), "=r"(r[1]), "=r"(r[2]), "=r"(r[3]) : "r"(addr));
}
__device__ __forceinline__ void mma16816(float* c, const uint32_t* a, const uint32_t* b) {
    asm volatile(
        "mma.sync.aligned.m16n8k16.row.col.f32.bf16.bf16.f32 "
        "{%0,%1,%2,%3}, {%4,%5,%6,%7}, {%8,%9}, {%0,%1,%2,%3};"
        : "+f"(c[0]), "+f"(c[1]), "+f"(c[2]), "+f"(c[3])
        : "r"(a[0]), "r"(a[1]), "r"(a[2]), "r"(a[3]), "r"(b[0]), "r"(b[1]));
}

// ---------------- kernel 1: fp32 -> (hi, lo) bf16 with F<->M transpose ----------------
__global__ void convert_kernel(const float* __restrict__ m1, const float* __restrict__ m2)
{
    __shared__ float tile[32][33];
    const int z = blockIdx.z >> 6;
    const int bat = blockIdx.z & 63;
    const float* __restrict__ src = z ? m2 : m1;
    const int m0 = blockIdx.x * 32;
    const int f0 = blockIdx.y * 32;
    const int tx = threadIdx.x, ty = threadIdx.y;

#pragma unroll
    for (int i = 0; i < 4; i++) {
        int f = f0 + ty + i * 8;
        tile[ty + i * 8][tx] = src[((size_t)bat * FDIM + f) * MDIM + m0 + tx];
    }
    __syncthreads();
#pragma unroll
    for (int i = 0; i < 4; i++) {
        int m = m0 + ty + i * 8;
        int f = f0 + tx;
        float x = tile[tx][ty + i * 8];
        __nv_bfloat16 h = __float2bfloat16(x);
        float r = x - __bfloat162float(h);
        size_t o = (((size_t)(z * BSZ + bat) * MDIM) + m) * FDIM + f;
        g_hi[o] = h;
        g_lo[o] = __float2bfloat16(r);
    }
}

// ---------------- kernel 2: pair GEMM (ldmatrix + cp.async pipeline) + hist ----------------
__global__ __launch_bounds__(256, 2)
void pair_hist_mma_kernel(float* __restrict__ out)
{
    // triangular pair decode: blockIdx.x in [0, 2080) -> (a <= b)
    const int idx = blockIdx.x;
    int a = (int)((2.0f * BSZ + 1.0f -
                   sqrtf((float)((2 * BSZ + 1) * (2 * BSZ + 1) - 8 * idx))) * 0.5f);
    while (STARTROW(a + 1) <= idx) ++a;
    while (STARTROW(a) > idx) --a;
    const int b = a + (idx - STARTROW(a));
    const int z = blockIdx.y;

    extern __shared__ char dsm[];
    const uint32_t sbase = smem_u32(dsm);

    __shared__ float wmn[8], wmx[8];
    __shared__ float s_mn, s_sc;
    __shared__ unsigned int bins[8];

    const int tid  = threadIdx.x;
    const int wid  = tid >> 5;
    const int lane = tid & 31;
    const int wm   = wid & 1;            // 2 warp-rows (64 m)
    const int wn   = wid >> 1;           // 4 warp-cols (32 n)

    if (tid < 8) bins[tid] = 0u;

    // gmem bases (uint4 = 8 bf16); row stride = 256 bf16 = 32 uint4
    const uint4* gAhi = (const uint4*)g_hi + (size_t)(z * BSZ + a) * MDIM * 32;
    const uint4* gAlo = (const uint4*)g_lo + (size_t)(z * BSZ + a) * MDIM * 32;
    const uint4* gBhi = (const uint4*)g_hi + (size_t)(z * BSZ + b) * MDIM * 32;
    const uint4* gBlo = (const uint4*)g_lo + (size_t)(z * BSZ + b) * MDIM * 32;

    // per-thread cp.async coordinates: 2 iters x (m = j>>2, g = j&3)
    const int j0 = tid, j1 = tid + 256;
    const int m0c = j0 >> 2, g0c = j0 & 3;
    const int m1c = j1 >> 2, g1c = j1 & 3;
    const int so0 = m0c * PITCHB + g0c * 16;
    const int so1 = m1c * PITCHB + g1c * 16;

    // LDSM lane address components
    const int lq = lane >> 3, lr = lane & 7;
    const int aoff = (lr + (lq & 1) * 8) * PITCHB + (lq >> 1) * 16;   // A: a0,a1,a2,a3 order
    const int boff = (lr + (lq >> 1) * 8) * PITCHB + (lq & 1) * 16;   // B: 2 n-tiles per x4

    float acc[4][4][4];
#pragma unroll
    for (int i = 0; i < 4; i++)
#pragma unroll
        for (int jj = 0; jj < 4; jj++)
#pragma unroll
            for (int q = 0; q < 4; q++) acc[i][jj][q] = 0.0f;

    // issue one chunk's cp.asyncs into stage buffer
    auto issue = [&](int c, int buf) {
        uint32_t sb = sbase + buf * BUFB;
        int gi0 = m0c * 32 + c * 4 + g0c;
        int gi1 = m1c * 32 + c * 4 + g1c;
        cp16(sb + 0 * TILEB + so0, gAhi + gi0);
        cp16(sb + 0 * TILEB + so1, gAhi + gi1);
        cp16(sb + 1 * TILEB + so0, gAlo + gi0);
        cp16(sb + 1 * TILEB + so1, gAlo + gi1);
        cp16(sb + 2 * TILEB + so0, gBhi + gi0);
        cp16(sb + 2 * TILEB + so1, gBhi + gi1);
        cp16(sb + 3 * TILEB + so0, gBlo + gi0);
        cp16(sb + 3 * TILEB + so1, gBlo + gi1);
        CP_COMMIT();
    };

    issue(0, 0);
    issue(1, 1);

    for (int c = 0; c < NCHUNK; c++) {
        if (c < NCHUNK - 1) { CP_WAIT1(); } else { CP_WAIT0(); }
        __syncthreads();

        const uint32_t sb   = sbase + (c & 1) * BUFB;
        const uint32_t sAhi = sb;
        const uint32_t sAlo = sb + TILEB;
        const uint32_t sBhi = sb + 2 * TILEB;
        const uint32_t sBlo = sb + 3 * TILEB;

#pragma unroll
        for (int ks = 0; ks < KC / 16; ks++) {
            const int kadd = ks * 32;

            // B fragments: 2 LDSM.x4 each for hi/lo cover all 4 n-tiles
            uint32_t Bh[4][2], Bl[4][2];
#pragma unroll
            for (int h = 0; h < 2; h++) {
                uint32_t r4[4];
                uint32_t addr = sBhi + (wn * 32 + h * 16) * PITCHB + boff + kadd;
                ldsm_x4(r4, addr);
                Bh[h * 2 + 0][0] = r4[0]; Bh[h * 2 + 0][1] = r4[1];
                Bh[h * 2 + 1][0] = r4[2]; Bh[h * 2 + 1][1] = r4[3];
                addr = sBlo + (wn * 32 + h * 16) * PITCHB + boff + kadd;
                ldsm_x4(r4, addr);
                Bl[h * 2 + 0][0] = r4[0]; Bl[h * 2 + 0][1] = r4[1];
                Bl[h * 2 + 1][0] = r4[2]; Bl[h * 2 + 1][1] = r4[3];
            }

#pragma unroll
            for (int mt = 0; mt < 4; mt++) {
                const int mrow = (wm * 64 + mt * 16) * PITCHB + aoff + kadd;
                uint32_t Ah[4], Al[4];
                ldsm_x4(Ah, sAhi + mrow);
                ldsm_x4(Al, sAlo + mrow);
#pragma unroll
                for (int nt = 0; nt < 4; nt++) {
                    mma16816(acc[mt][nt], Ah, Bh[nt]);   // hi*hi
                    mma16816(acc[mt][nt], Ah, Bl[nt]);   // hi*lo
                    mma16816(acc[mt][nt], Al, Bh[nt]);   // lo*hi
                }
            }
        }
        __syncthreads();
        if (c + 2 < NCHUNK) issue(c + 2, c & 1);
    }

    // ---- min/max over the 128x128 tile (values in registers) ----
    float mn = 3.4e38f, mx = -3.4e38f;
#pragma unroll
    for (int i = 0; i < 4; i++)
#pragma unroll
        for (int jj = 0; jj < 4; jj++)
#pragma unroll
            for (int q = 0; q < 4; q++) {
                float v = acc[i][jj][q];
                mn = fminf(mn, v);
                mx = fmaxf(mx, v);
            }
#pragma unroll
    for (int o = 16; o > 0; o >>= 1) {
        mn = fminf(mn, __shfl_xor_sync(0xffffffffu, mn, o));
        mx = fmaxf(mx, __shfl_xor_sync(0xffffffffu, mx, o));
    }
    if (lane == 0) { wmn[wid] = mn; wmx[wid] = mx; }
    __syncthreads();
    if (tid == 0) {
        float m0 = wmn[0], M0 = wmx[0];
#pragma unroll
        for (int w = 1; w < 8; w++) {
            m0 = fminf(m0, wmn[w]);
            M0 = fmaxf(M0, wmx[w]);
        }
        float den = (M0 > m0) ? (M0 - m0) : 1.0f;
        s_mn = m0;
        s_sc = 8.0f / den;
    }
    __syncthreads();

    // ---- binning into byte-packed counters (64 values/thread, max 64/bin) ----
    const float mnv = s_mn, sc = s_sc;
    unsigned int c0 = 0, c1 = 0;
#pragma unroll
    for (int i = 0; i < 4; i++)
#pragma unroll
        for (int jj = 0; jj < 4; jj++)
#pragma unroll
            for (int q = 0; q < 4; q++) {
                float t = (acc[i][jj][q] - mnv) * sc;
                int bidx = (int)floorf(t);
                bidx = bidx < 0 ? 0 : (bidx > 7 ? 7 : bidx);
                unsigned int inc = 1u << ((bidx & 3) * 8);
                if (bidx < 4) c0 += inc; else c1 += inc;
            }
#pragma unroll
    for (int bbin = 0; bbin < 8; bbin++) {
        unsigned int v = (bbin < 4) ? ((c0 >> (bbin * 8)) & 0xFFu)
                                    : ((c1 >> ((bbin - 4) * 8)) & 0xFFu);
#pragma unroll
        for (int o = 16; o > 0; o >>= 1)
            v += __shfl_xor_sync(0xffffffffu, v, o);
        if (lane == 0) atomicAdd(&bins[bbin], v);
    }
    __syncthreads();

    // ---- L2 normalize, write both (a,b) and (b,a) rows ----
    if (tid == 0) {
        float h[8], ss = 0.0f;
#pragma unroll
        for (int k = 0; k < 8; k++) { h[k] = (float)bins[k]; ss += h[k] * h[k]; }
        float nrm = fmaxf(sqrtf(ss), 1e-12f);
        const int row1 = (a * BSZ + b) * 16 + z * 8;
        const int row2 = (b * BSZ + a) * 16 + z * 8;
#pragma unroll
        for (int k = 0; k < 8; k++) {
            float v = h[k] / nrm;
            out[row1 + k] = v;
            out[row2 + k] = v;
        }
    }
}

// ---------------- launch ----------------
extern "C" void kernel_launch(void* const* d_in, const int* in_sizes, int n_in,
                              void* d_out, int out_size)
{
    const float* m1 = (const float*)d_in[0];
    const float* m2 = (const float*)d_in[1];
    float* out = (float*)d_out;

    convert_kernel<<<dim3(MDIM / 32, FDIM / 32, 2 * BSZ), dim3(32, 8)>>>(m1, m2);

    cudaFuncSetAttribute(pair_hist_mma_kernel,
                         cudaFuncAttributeMaxDynamicSharedMemorySize, SMEM_DYN);
    pair_hist_mma_kernel<<<dim3(NPAIR, 2, 1), 256, SMEM_DYN>>>(out);
}

// round 12
// speedup vs baseline: 1.0049x; 1.0049x over previous
#include <cuda_runtime.h>
#include <cuda_bf16.h>
#include <math.h>
#include <stdint.h>

// ---------------- problem constants ----------------
#define BSZ   64
#define FDIM  256
#define MDIM  128
#define KC    32                    // K elements per chunk
#define NCHUNK (FDIM / KC)          // 8
#define PITCHB 80                   // bytes per smem row (64B data + 16B pad, LDSM conflict-free)
#define TILEB  (MDIM * PITCHB)      // 10240 B per operand tile
#define BUFB   (4 * TILEB)          // 40960 B per stage (Ahi,Alo,Bhi,Blo)
#define SMEM_DYN (2 * BUFB)         // 81920 B double-buffered

#define NPAIR (BSZ * (BSZ + 1) / 2) // 2080
#define STARTROW(x) ((x) * BSZ - (x) * ((x) - 1) / 2)

// bf16 hi/lo scratch, K-major: [z][batch][m][f]  (8 MB each)
__device__ __nv_bfloat16 g_hi[2u * BSZ * MDIM * FDIM];
__device__ __nv_bfloat16 g_lo[2u * BSZ * MDIM * FDIM];

// ---------------- helpers ----------------
__device__ __forceinline__ uint32_t smem_u32(const void* p) {
    uint32_t a;
    asm("{ .reg .u64 t; cvta.to.shared.u64 t, %1; cvt.u32.u64 %0, t; }" : "=r"(a) : "l"(p));
    return a;
}
__device__ __forceinline__ void cp16(uint32_t s, const void* g) {
    asm volatile("cp.async.cg.shared.global [%0], [%1], 16;" :: "r"(s), "l"(g));
}
#define CP_COMMIT() asm volatile("cp.async.commit_group;" ::: "memory")
#define CP_WAIT1()  asm volatile("cp.async.wait_group 1;" ::: "memory")
#define CP_WAIT0()  asm volatile("cp.async.wait_group 0;" ::: "memory")

__device__ __forceinline__ void ldsm_x4(uint32_t* r, uint32_t addr) {
    asm volatile("ldmatrix.sync.aligned.m8n8.x4.shared.b16 {%0,%1,%2,%3}, [%4];"
                 : "=r"(r[0]), "=r"(r[1]), "=r"(r[2]), "=r"(r[3]) : "r"(addr));
}
__device__ __forceinline__ void mma16816(float* c, const uint32_t* a, const uint32_t* b) {
    asm volatile(
        "mma.sync.aligned.m16n8k16.row.col.f32.bf16.bf16.f32 "
        "{%0,%1,%2,%3}, {%4,%5,%6,%7}, {%8,%9}, {%0,%1,%2,%3};"
        : "+f"(c[0]), "+f"(c[1]), "+f"(c[2]), "+f"(c[3])
        : "r"(a[0]), "r"(a[1]), "r"(a[2]), "r"(a[3]), "r"(b[0]), "r"(b[1]));
}

// ---------------- kernel 1: fp32 -> (hi, lo) bf16 with F<->M transpose ----------------
__global__ void convert_kernel(const float* __restrict__ m1, const float* __restrict__ m2)
{
    __shared__ float tile[32][33];
    const int z = blockIdx.z >> 6;
    const int bat = blockIdx.z & 63;
    const float* __restrict__ src = z ? m2 : m1;
    const int m0 = blockIdx.x * 32;
    const int f0 = blockIdx.y * 32;
    const int tx = threadIdx.x, ty = threadIdx.y;

#pragma unroll
    for (int i = 0; i < 4; i++) {
        int f = f0 + ty + i * 8;
        tile[ty + i * 8][tx] = src[((size_t)bat * FDIM + f) * MDIM + m0 + tx];
    }
    __syncthreads();
#pragma unroll
    for (int i = 0; i < 4; i++) {
        int m = m0 + ty + i * 8;
        int f = f0 + tx;
        float x = tile[tx][ty + i * 8];
        __nv_bfloat16 h = __float2bfloat16(x);
        float r = x - __bfloat162float(h);
        size_t o = (((size_t)(z * BSZ + bat) * MDIM) + m) * FDIM + f;
        g_hi[o] = h;
        g_lo[o] = __float2bfloat16(r);
    }
}

// ---------------- kernel 2: pair GEMM (ldmatrix + cp.async pipeline) + hist ----------------
__global__ __launch_bounds__(256, 2)
void pair_hist_mma_kernel(float* __restrict__ out)
{
    // triangular pair decode: blockIdx.x in [0, 2080) -> (a <= b)
    const int idx = blockIdx.x;
    int a = (int)((2.0f * BSZ + 1.0f -
                   sqrtf((float)((2 * BSZ + 1) * (2 * BSZ + 1) - 8 * idx))) * 0.5f);
    while (STARTROW(a + 1) <= idx) ++a;
    while (STARTROW(a) > idx) --a;
    const int b = a + (idx - STARTROW(a));
    const int z = blockIdx.y;

    extern __shared__ char dsm[];
    const uint32_t sbase = smem_u32(dsm);

    __shared__ float wmn[8], wmx[8];
    __shared__ float s_mn, s_sc;
    __shared__ unsigned int bins[8];

    const int tid  = threadIdx.x;
    const int wid  = tid >> 5;
    const int lane = tid & 31;
    const int wm   = wid & 1;            // 2 warp-rows (64 m)
    const int wn   = wid >> 1;           // 4 warp-cols (32 n)

    if (tid < 8) bins[tid] = 0u;

    // gmem bases (uint4 = 8 bf16); row stride = 256 bf16 = 32 uint4
    const uint4* gAhi = (const uint4*)g_hi + (size_t)(z * BSZ + a) * MDIM * 32;
    const uint4* gAlo = (const uint4*)g_lo + (size_t)(z * BSZ + a) * MDIM * 32;
    const uint4* gBhi = (const uint4*)g_hi + (size_t)(z * BSZ + b) * MDIM * 32;
    const uint4* gBlo = (const uint4*)g_lo + (size_t)(z * BSZ + b) * MDIM * 32;

    // per-thread cp.async coordinates: 2 iters x (m = j>>2, g = j&3)
    const int j0 = tid, j1 = tid + 256;
    const int m0c = j0 >> 2, g0c = j0 & 3;
    const int m1c = j1 >> 2, g1c = j1 & 3;
    const int so0 = m0c * PITCHB + g0c * 16;
    const int so1 = m1c * PITCHB + g1c * 16;

    // LDSM lane address components
    const int lq = lane >> 3, lr = lane & 7;
    const int aoff = (lr + (lq & 1) * 8) * PITCHB + (lq >> 1) * 16;   // A: a0,a1,a2,a3 order
    const int boff = (lr + (lq >> 1) * 8) * PITCHB + (lq & 1) * 16;   // B: 2 n-tiles per x4

    float acc[4][4][4];
#pragma unroll
    for (int i = 0; i < 4; i++)
#pragma unroll
        for (int jj = 0; jj < 4; jj++)
#pragma unroll
            for (int q = 0; q < 4; q++) acc[i][jj][q] = 0.0f;

    // issue one chunk's cp.asyncs into stage buffer
    auto issue = [&](int c, int buf) {
        uint32_t sb = sbase + buf * BUFB;
        int gi0 = m0c * 32 + c * 4 + g0c;
        int gi1 = m1c * 32 + c * 4 + g1c;
        cp16(sb + 0 * TILEB + so0, gAhi + gi0);
        cp16(sb + 0 * TILEB + so1, gAhi + gi1);
        cp16(sb + 1 * TILEB + so0, gAlo + gi0);
        cp16(sb + 1 * TILEB + so1, gAlo + gi1);
        cp16(sb + 2 * TILEB + so0, gBhi + gi0);
        cp16(sb + 2 * TILEB + so1, gBhi + gi1);
        cp16(sb + 3 * TILEB + so0, gBlo + gi0);
        cp16(sb + 3 * TILEB + so1, gBlo + gi1);
        CP_COMMIT();
    };

    issue(0, 0);
    issue(1, 1);

    for (int c = 0; c < NCHUNK; c++) {
        if (c < NCHUNK - 1) { CP_WAIT1(); } else { CP_WAIT0(); }
        __syncthreads();

        const uint32_t sb   = sbase + (c & 1) * BUFB;
        const uint32_t sAhi = sb;
        const uint32_t sAlo = sb + TILEB;
        const uint32_t sBhi = sb + 2 * TILEB;
        const uint32_t sBlo = sb + 3 * TILEB;

#pragma unroll
        for (int ks = 0; ks < KC / 16; ks++) {
            const int kadd = ks * 32;

            // B fragments: 2 LDSM.x4 each for hi/lo cover all 4 n-tiles
            uint32_t Bh[4][2], Bl[4][2];
#pragma unroll
            for (int h = 0; h < 2; h++) {
                uint32_t r4[4];
                uint32_t addr = sBhi + (wn * 32 + h * 16) * PITCHB + boff + kadd;
                ldsm_x4(r4, addr);
                Bh[h * 2 + 0][0] = r4[0]; Bh[h * 2 + 0][1] = r4[1];
                Bh[h * 2 + 1][0] = r4[2]; Bh[h * 2 + 1][1] = r4[3];
                addr = sBlo + (wn * 32 + h * 16) * PITCHB + boff + kadd;
                ldsm_x4(r4, addr);
                Bl[h * 2 + 0][0] = r4[0]; Bl[h * 2 + 0][1] = r4[1];
                Bl[h * 2 + 1][0] = r4[2]; Bl[h * 2 + 1][1] = r4[3];
            }

#pragma unroll
            for (int mt = 0; mt < 4; mt++) {
                const int mrow = (wm * 64 + mt * 16) * PITCHB + aoff + kadd;
                uint32_t Ah[4], Al[4];
                ldsm_x4(Ah, sAhi + mrow);
                ldsm_x4(Al, sAlo + mrow);
#pragma unroll
                for (int nt = 0; nt < 4; nt++) {
                    mma16816(acc[mt][nt], Ah, Bh[nt]);   // hi*hi
                    mma16816(acc[mt][nt], Ah, Bl[nt]);   // hi*lo
                    mma16816(acc[mt][nt], Al, Bh[nt]);   // lo*hi
                }
            }
        }
        __syncthreads();
        if (c + 2 < NCHUNK) issue(c + 2, c & 1);
    }

    // ---- min/max over the 128x128 tile (values in registers) ----
    float mn = 3.4e38f, mx = -3.4e38f;
#pragma unroll
    for (int i = 0; i < 4; i++)
#pragma unroll
        for (int jj = 0; jj < 4; jj++)
#pragma unroll
            for (int q = 0; q < 4; q++) {
                float v = acc[i][jj][q];
                mn = fminf(mn, v);
                mx = fmaxf(mx, v);
            }
#pragma unroll
    for (int o = 16; o > 0; o >>= 1) {
        mn = fminf(mn, __shfl_xor_sync(0xffffffffu, mn, o));
        mx = fmaxf(mx, __shfl_xor_sync(0xffffffffu, mx, o));
    }
    if (lane == 0) { wmn[wid] = mn; wmx[wid] = mx; }
    __syncthreads();
    if (tid == 0) {
        float m0 = wmn[0], M0 = wmx[0];
#pragma unroll
        for (int w = 1; w < 8; w++) {
            m0 = fminf(m0, wmn[w]);
            M0 = fmaxf(M0, wmx[w]);
        }
        float den = (M0 > m0) ? (M0 - m0) : 1.0f;
        s_mn = m0;
        s_sc = 8.0f / den;
    }
    __syncthreads();

    // ---- binning into byte-packed counters (64 values/thread, max 64/bin) ----
    const float mnv = s_mn, sc = s_sc;
    unsigned int c0 = 0, c1 = 0;
#pragma unroll
    for (int i = 0; i < 4; i++)
#pragma unroll
        for (int jj = 0; jj < 4; jj++)
#pragma unroll
            for (int q = 0; q < 4; q++) {
                float t = (acc[i][jj][q] - mnv) * sc;
                int bidx = (int)floorf(t);
                bidx = bidx < 0 ? 0 : (bidx > 7 ? 7 : bidx);
                unsigned int inc = 1u << ((bidx & 3) * 8);
                if (bidx < 4) c0 += inc; else c1 += inc;
            }
#pragma unroll
    for (int bbin = 0; bbin < 8; bbin++) {
        unsigned int v = (bbin < 4) ? ((c0 >> (bbin * 8)) & 0xFFu)
                                    : ((c1 >> ((bbin - 4) * 8)) & 0xFFu);
#pragma unroll
        for (int o = 16; o > 0; o >>= 1)
            v += __shfl_xor_sync(0xffffffffu, v, o);
        if (lane == 0) atomicAdd(&bins[bbin], v);
    }
    __syncthreads();

    // ---- L2 normalize, write both (a,b) and (b,a) rows ----
    if (tid == 0) {
        float h[8], ss = 0.0f;
#pragma unroll
        for (int k = 0; k < 8; k++) { h[k] = (float)bins[k]; ss += h[k] * h[k]; }
        float nrm = fmaxf(sqrtf(ss), 1e-12f);
        const int row1 = (a * BSZ + b) * 16 + z * 8;
        const int row2 = (b * BSZ + a) * 16 + z * 8;
#pragma unroll
        for (int k = 0; k < 8; k++) {
            float v = h[k] / nrm;
            out[row1 + k] = v;
            out[row2 + k] = v;
        }
    }
}

// ---------------- launch ----------------
extern "C" void kernel_launch(void* const* d_in, const int* in_sizes, int n_in,
                              void* d_out, int out_size)
{
    const float* m1 = (const float*)d_in[0];
    const float* m2 = (const float*)d_in[1];
    float* out = (float*)d_out;

    convert_kernel<<<dim3(MDIM / 32, FDIM / 32, 2 * BSZ), dim3(32, 8)>>>(m1, m2);

    cudaFuncSetAttribute(pair_hist_mma_kernel,
                         cudaFuncAttributeMaxDynamicSharedMemorySize, SMEM_DYN);
    pair_hist_mma_kernel<<<dim3(NPAIR, 2, 1), 256, SMEM_DYN>>>(out);
}